// round 13
// baseline (speedup 1.0000x reference)
#include <cuda_runtime.h>
#include <cuda_fp16.h>
#include <cstdint>

#define BB   2
#define SS   2048
#define HH   1024
#define NHH  16
#define DHH  64
#define NT   (SS/64)

// fp16 scratch. Q pre-scaled by log2(e)/8 (log2-domain scores).
__device__ __half g_q[BB*NHH*SS*DHH];
__device__ __half g_k[BB*NHH*SS*DHH];
__device__ __half g_v[BB*NHH*SS*DHH];     // V transposed [B,NH,DH,S]
__device__ __half g_hid[BB*SS*HH];
__device__ __half g_wq[HH*HH];
__device__ __half g_wk[HH*HH];
__device__ __half g_wv[HH*HH];

#define L2E 1.4426950408889634f

__device__ __forceinline__ void mma_f16(float* c,
    unsigned a0, unsigned a1, unsigned a2, unsigned a3,
    unsigned b0, unsigned b1)
{
    asm volatile(
        "mma.sync.aligned.m16n8k16.row.col.f32.f16.f16.f32 "
        "{%0,%1,%2,%3}, {%4,%5,%6,%7}, {%8,%9}, {%0,%1,%2,%3};"
        : "+f"(c[0]), "+f"(c[1]), "+f"(c[2]), "+f"(c[3])
        : "r"(a0), "r"(a1), "r"(a2), "r"(a3), "r"(b0), "r"(b1));
}

__device__ __forceinline__ void ldsm_x4(unsigned& r0, unsigned& r1,
                                        unsigned& r2, unsigned& r3, uint32_t a)
{
    asm volatile("ldmatrix.sync.aligned.m8n8.x4.shared.b16 {%0,%1,%2,%3}, [%4];"
        : "=r"(r0), "=r"(r1), "=r"(r2), "=r"(r3) : "r"(a));
}

__device__ __forceinline__ uint32_t smem_u32(const void* p) {
    return (uint32_t)__cvta_generic_to_shared(p);
}
__device__ __forceinline__ void cpa16(uint32_t s, const void* g) {
    asm volatile("cp.async.ca.shared.global [%0], [%1], 16;" :: "r"(s), "l"(g));
}
#define CP_COMMIT() asm volatile("cp.async.commit_group;")
#define CP_WAIT0()  asm volatile("cp.async.wait_group 0;")
#define CP_WAIT1()  asm volatile("cp.async.wait_group 1;")

__device__ __forceinline__ unsigned packh2(float lo, float hi) {
    __half2 h = __floats2half2_rn(lo, hi);
    return *(unsigned*)&h;
}

__device__ __forceinline__ float fexp2(float y) {
    float r;
    asm("ex2.approx.f32 %0, %1;" : "=f"(r) : "f"(y));
    return r;
}

// ---------------------------------------------------------------------------
// One-time fp32 -> fp16 conversion of hid and the three weight matrices.
// ---------------------------------------------------------------------------
__global__ __launch_bounds__(256) void cvt_kernel(
    const float* __restrict__ hid, const float* __restrict__ wq,
    const float* __restrict__ wk, const float* __restrict__ wv)
{
    const float* src; __half* dst; int n;
    switch (blockIdx.y) {
        case 0:  src = hid; dst = g_hid; n = BB*SS*HH; break;
        case 1:  src = wq;  dst = g_wq;  n = HH*HH;    break;
        case 2:  src = wk;  dst = g_wk;  n = HH*HH;    break;
        default: src = wv;  dst = g_wv;  n = HH*HH;    break;
    }
    int i = (blockIdx.x*256 + threadIdx.x)*8;
    if (i >= n) return;
    float4 v0 = *(const float4*)(src + i);
    float4 v1 = *(const float4*)(src + i + 4);
    uint4 u;
    u.x = packh2(v0.x, v0.y); u.y = packh2(v0.z, v0.w);
    u.z = packh2(v1.x, v1.y); u.w = packh2(v1.z, v1.w);
    *(uint4*)(dst + i) = u;
}

// ---------------------------------------------------------------------------
// QKV projection (unchanged): fp16 GEMM, CTA 128x128, ktile 64, 8 warps 2x4.
// ---------------------------------------------------------------------------
#define KT    64
#define QSTR  36
#define QSTG  (128*QSTR)
#define QKV_SMEM_U32 (4*QSTG)

__global__ __launch_bounds__(256, 2) void qkv_kernel(
    const float* __restrict__ bq, const float* __restrict__ bk,
    const float* __restrict__ bv)
{
    const __half* Wsrc; const float* bsrc;
    if (blockIdx.z == 0)      { Wsrc = g_wq; bsrc = bq; }
    else if (blockIdx.z == 1) { Wsrc = g_wk; bsrc = bk; }
    else                      { Wsrc = g_wv; bsrc = bv; }

    extern __shared__ unsigned smq[];
    unsigned* As  = smq;
    unsigned* Bsm = smq + 2*QSTG;

    const int tid  = threadIdx.x;
    const int warp = tid >> 5;
    const int lane = tid & 31;
    const int gid  = lane >> 2;
    const int tg   = lane & 3;
    const int m0   = blockIdx.y * 128;
    const int n0   = blockIdx.x * 128;
    const int m0w  = (warp >> 2) * 64;
    const int n0w  = (warp & 3) * 32;

    const __half* Ah = g_hid + (size_t)m0 * HH;
    const __half* Bh = Wsrc  + (size_t)n0 * HH;

    const uint32_t as_b = smem_u32(As);
    const uint32_t bs_b = smem_u32(Bsm);

    const int crow = tid >> 3;
    const int cc   = tid & 7;

    #pragma unroll
    for (int it = 0; it < 4; it++) {
        int row = crow + it*32;
        cpa16(as_b + (uint32_t)(row*QSTR + cc*4)*4, Ah + (size_t)row*HH + cc*8);
        cpa16(bs_b + (uint32_t)(row*QSTR + cc*4)*4, Bh + (size_t)row*HH + cc*8);
    }
    CP_COMMIT();

    float acc[4][4][4];
    #pragma unroll
    for (int i = 0; i < 4; i++)
        #pragma unroll
        for (int j = 0; j < 4; j++)
            #pragma unroll
            for (int e = 0; e < 4; e++) acc[i][j][e] = 0.0f;

    const int row16 = lane & 15, c16 = lane >> 4;
    const int lrow8 = lane & 7,  lgrp8 = lane >> 3;
    const uint32_t a_ld = (uint32_t)((m0w + row16)*QSTR)*4 + c16*16;
    const uint32_t b_ld = (uint32_t)((n0w + lrow8)*QSTR)*4 + lgrp8*16;

    for (int kt = 0; kt < HH/KT; kt++) {
        const int cur = kt & 1;

        __syncthreads();
        if (kt + 1 < HH/KT) {
            const int nxt = cur ^ 1;
            const int kof = (kt + 1) * KT;
            #pragma unroll
            for (int it = 0; it < 4; it++) {
                int row = crow + it*32;
                cpa16(as_b + (uint32_t)(nxt*QSTG + row*QSTR + cc*4)*4,
                      Ah + (size_t)row*HH + kof + cc*8);
                cpa16(bs_b + (uint32_t)(nxt*QSTG + row*QSTR + cc*4)*4,
                      Bh + (size_t)row*HH + kof + cc*8);
            }
            CP_COMMIT();
            CP_WAIT1();
        } else {
            CP_WAIT0();
        }
        __syncthreads();

        const uint32_t ab = as_b + (uint32_t)(cur*QSTG)*4;
        const uint32_t bb = bs_b + (uint32_t)(cur*QSTG)*4;

        #pragma unroll
        for (int kp = 0; kp < 2; kp++) {
            unsigned bf[4][4];
            #pragma unroll
            for (int nt = 0; nt < 4; nt++)
                ldsm_x4(bf[nt][0], bf[nt][1], bf[nt][2], bf[nt][3],
                        bb + b_ld + (uint32_t)(nt*8*QSTR)*4 + kp*64);
            #pragma unroll
            for (int kh = 0; kh < 2; kh++) {
                unsigned af[4][4];
                #pragma unroll
                for (int mf = 0; mf < 4; mf++)
                    ldsm_x4(af[mf][0], af[mf][1], af[mf][2], af[mf][3],
                            ab + a_ld + (uint32_t)(mf*16*QSTR)*4 + (kp*2+kh)*32);
                #pragma unroll
                for (int mf = 0; mf < 4; mf++)
                    #pragma unroll
                    for (int nt = 0; nt < 4; nt++)
                        mma_f16(acc[mf][nt], af[mf][0], af[mf][1], af[mf][2],
                                af[mf][3], bf[nt][kh*2], bf[nt][kh*2+1]);
            }
        }
    }

    const int head  = blockIdx.x*2 + (n0w >> 6);
    const int dbase = n0w & 63;

    #pragma unroll
    for (int mf = 0; mf < 4; mf++) {
        int m    = m0 + m0w + mf*16 + gid;
        int bat0 = m >> 11,     srow0 = m & (SS-1);
        int bat1 = (m+8) >> 11, srow1 = (m+8) & (SS-1);

        if (blockIdx.z == 2) {
            size_t base0 = ((size_t)bat0*NHH + head)*DHH;
            size_t base1 = ((size_t)bat1*NHH + head)*DHH;
            #pragma unroll
            for (int nt = 0; nt < 4; nt++) {
                int d = dbase + nt*8 + tg*2;
                int ng = n0 + n0w + nt*8 + tg*2;
                float b0 = bsrc[ng], b1 = bsrc[ng+1];
                g_v[(base0 + d    )*SS + srow0] = __float2half_rn(acc[mf][nt][0]+b0);
                g_v[(base0 + d + 1)*SS + srow0] = __float2half_rn(acc[mf][nt][1]+b1);
                g_v[(base1 + d    )*SS + srow1] = __float2half_rn(acc[mf][nt][2]+b0);
                g_v[(base1 + d + 1)*SS + srow1] = __float2half_rn(acc[mf][nt][3]+b1);
            }
        } else {
            __half* outp = (blockIdx.z == 0) ? g_q : g_k;
            const float qscale = (blockIdx.z == 0) ? (0.125f * L2E) : 1.0f;
            size_t rb0 = (((size_t)bat0*NHH+head)*SS+srow0)*DHH;
            size_t rb1 = (((size_t)bat1*NHH+head)*SS+srow1)*DHH;
            #pragma unroll
            for (int nt = 0; nt < 4; nt++) {
                int d = dbase + nt*8 + tg*2;
                int ng = n0 + n0w + nt*8 + tg*2;
                float b0 = bsrc[ng], b1 = bsrc[ng+1];
                *(unsigned*)&outp[rb0 + d] =
                    packh2((acc[mf][nt][0]+b0)*qscale, (acc[mf][nt][1]+b1)*qscale);
                *(unsigned*)&outp[rb1 + d] =
                    packh2((acc[mf][nt][2]+b0)*qscale, (acc[mf][nt][3]+b1)*qscale);
            }
        }
    }
}

// ---------------------------------------------------------------------------
// Attention (round-12 winner + row-sums via ones-column MMA on tensor pipe:
// no scalar lsum chains, no epilogue shuffles).
// ---------------------------------------------------------------------------
#define STR  36
#define BSTR 68
#define SM_K (64*STR)
#define SM_V (64*STR)
#define SM_B (128*BSTR)
#define OFF_K 0
#define OFF_V (2*SM_K)
#define OFF_B (OFF_V + 2*SM_V)
#define ATTN_SMEM_U32 (OFF_B + 2*SM_B)

__global__ __launch_bounds__(256, 2) void attn_kernel(
    const float* __restrict__ bias, float* __restrict__ out)
{
    extern __shared__ unsigned sm[];
    unsigned* Ks = sm + OFF_K;
    unsigned* Vs = sm + OFF_V;
    float*    Bs = (float*)(sm + OFF_B);

    const int tid  = threadIdx.x;
    const int warp = tid >> 5;
    const int lane = tid & 31;
    const int gid  = lane >> 2;
    const int tg   = lane & 3;
    // batch = fastest grid bit: the two CTAs sharing a bias slice are
    // adjacent bids -> same wave, nearby SMs, lockstep bias stream.
    const int b    = blockIdx.x & 1;
    const int q0   = (blockIdx.x >> 1) * 128;
    const int h    = blockIdx.y;
    const int mw   = warp * 16;
    const int r0   = mw + gid, r1 = r0 + 8;

    const __half* Qg  = g_q + (((size_t)b*NHH + h)*SS + q0)*DHH;
    const __half* Kg  = g_k + (((size_t)b*NHH + h)*SS)*DHH;
    const __half* Vtg = g_v + (((size_t)b*NHH + h)*DHH)*SS;
    const float*  Bg  = bias + ((size_t)h*SS + q0)*SS;

    const uint32_t k_b = smem_u32(Ks);
    const uint32_t v_b = smem_u32(Vs);
    const uint32_t b_b = smem_u32(Bs);

    const int crow = tid >> 3;
    const int ccol = tid & 7;

    #pragma unroll
    for (int it = 0; it < 2; it++) {
        int row = crow + it*32;
        cpa16(k_b + (uint32_t)(row*STR + ccol*4)*4, Kg  + (size_t)row*DHH + ccol*8);
        cpa16(v_b + (uint32_t)(row*STR + ccol*4)*4, Vtg + (size_t)row*SS  + ccol*8);
    }
    #pragma unroll
    for (int i = 0; i < 8; i++) {
        int idx = tid + i*256;
        int row = idx >> 4, c = idx & 15;
        cpa16(b_b + (uint32_t)(row*BSTR + c*4)*4, Bg + (size_t)row*SS + c*4);
    }
    CP_COMMIT();

    unsigned qa[4][4];
    #pragma unroll
    for (int ks = 0; ks < 4; ks++) {
        qa[ks][0] = *(const unsigned*)(Qg + (size_t)r0*DHH + ks*16 + tg*2);
        qa[ks][1] = *(const unsigned*)(Qg + (size_t)r1*DHH + ks*16 + tg*2);
        qa[ks][2] = *(const unsigned*)(Qg + (size_t)r0*DHH + ks*16 + 8 + tg*2);
        qa[ks][3] = *(const unsigned*)(Qg + (size_t)r1*DHH + ks*16 + 8 + tg*2);
    }

    float acc[8][4];
    #pragma unroll
    for (int i = 0; i < 8; i++)
        #pragma unroll
        for (int j = 0; j < 4; j++) acc[i][j] = 0.0f;
    // row-sum accumulator (ones-column GEMM); all n-columns identical
    float acc9[4] = {0.0f, 0.0f, 0.0f, 0.0f};
    const unsigned ONES = 0x3C003C00u;   // half2(1.0, 1.0)

    const int lrow8 = lane & 7;
    const int lgrp  = lane >> 3;

    for (int kt = 0; kt < NT; kt++) {
        const int cur = kt & 1;
        const int kv0 = kt * 64;

        __syncthreads();
        if (kt + 1 < NT) {
            const int nxt = cur ^ 1;
            #pragma unroll
            for (int it = 0; it < 2; it++) {
                int row = crow + it*32;
                cpa16(k_b + (uint32_t)(nxt*SM_K + row*STR + ccol*4)*4,
                      Kg + (size_t)(kv0 + 64 + row)*DHH + ccol*8);
                cpa16(v_b + (uint32_t)(nxt*SM_V + row*STR + ccol*4)*4,
                      Vtg + (size_t)row*SS + kv0 + 64 + ccol*8);
            }
            #pragma unroll
            for (int i = 0; i < 8; i++) {
                int idx = tid + i*256;
                int row = idx >> 4, c = idx & 15;
                cpa16(b_b + (uint32_t)(nxt*SM_B + row*BSTR + c*4)*4,
                      Bg + (size_t)row*SS + kv0 + 64 + c*4);
            }
            CP_COMMIT();
            CP_WAIT1();
        } else {
            CP_WAIT0();
        }
        __syncthreads();

        const uint32_t kc = k_b + (uint32_t)(cur*SM_K)*4;
        const uint32_t vc = v_b + (uint32_t)(cur*SM_V)*4;
        const float*   Bc = Bs + (size_t)cur*SM_B;

        float s[8][4];
        #pragma unroll
        for (int nt = 0; nt < 8; nt++) {
            s[nt][0] = 0.0f; s[nt][1] = 0.0f; s[nt][2] = 0.0f; s[nt][3] = 0.0f;
            unsigned b0, b1, b2, b3, b4, b5, b6, b7;
            uint32_t base = kc + (uint32_t)((nt*8 + lrow8)*STR)*4 + lgrp*16;
            ldsm_x4(b0, b1, b2, b3, base);
            ldsm_x4(b4, b5, b6, b7, base + 64);
            mma_f16(s[nt], qa[0][0], qa[0][1], qa[0][2], qa[0][3], b0, b1);
            mma_f16(s[nt], qa[1][0], qa[1][1], qa[1][2], qa[1][3], b2, b3);
            mma_f16(s[nt], qa[2][0], qa[2][1], qa[2][2], qa[2][3], b4, b5);
            mma_f16(s[nt], qa[3][0], qa[3][1], qa[3][2], qa[3][3], b6, b7);
        }

        unsigned pa[4][4];
        #pragma unroll
        for (int nt = 0; nt < 8; nt++) {
            int c = nt*8 + tg*2;
            float2 bv0 = *(const float2*)(Bc + (size_t)r0*BSTR + c);
            float2 bv1 = *(const float2*)(Bc + (size_t)r1*BSTR + c);
            float p0 = fexp2(fmaf(bv0.x, L2E, s[nt][0]));
            float p1 = fexp2(fmaf(bv0.y, L2E, s[nt][1]));
            float p2 = fexp2(fmaf(bv1.x, L2E, s[nt][2]));
            float p3 = fexp2(fmaf(bv1.y, L2E, s[nt][3]));
            pa[nt >> 1][(nt & 1)*2 + 0] = packh2(p0, p1);
            pa[nt >> 1][(nt & 1)*2 + 1] = packh2(p2, p3);
        }

        // row sums on the tensor pipe: P x ones (no smem, no ldsm)
        mma_f16(acc9, pa[0][0], pa[0][1], pa[0][2], pa[0][3], ONES, ONES);
        mma_f16(acc9, pa[1][0], pa[1][1], pa[1][2], pa[1][3], ONES, ONES);
        mma_f16(acc9, pa[2][0], pa[2][1], pa[2][2], pa[2][3], ONES, ONES);
        mma_f16(acc9, pa[3][0], pa[3][1], pa[3][2], pa[3][3], ONES, ONES);

        #pragma unroll
        for (int nt = 0; nt < 8; nt++) {
            unsigned b0, b1, b2, b3, b4, b5, b6, b7;
            uint32_t base = vc + (uint32_t)((nt*8 + lrow8)*STR)*4 + lgrp*16;
            ldsm_x4(b0, b1, b2, b3, base);
            ldsm_x4(b4, b5, b6, b7, base + 64);
            mma_f16(acc[nt], pa[0][0], pa[0][1], pa[0][2], pa[0][3], b0, b1);
            mma_f16(acc[nt], pa[1][0], pa[1][1], pa[1][2], pa[1][3], b2, b3);
            mma_f16(acc[nt], pa[2][0], pa[2][1], pa[2][2], pa[2][3], b4, b5);
            mma_f16(acc[nt], pa[3][0], pa[3][1], pa[3][2], pa[3][3], b6, b7);
        }
    }

    float inv0 = 1.0f / acc9[0];
    float inv1 = 1.0f / acc9[2];

    int srow = q0 + r0;
    #pragma unroll
    for (int nt = 0; nt < 8; nt++) {
        int d = nt*8 + tg*2;
        float2 o0, o1;
        o0.x = acc[nt][0]*inv0; o0.y = acc[nt][1]*inv0;
        o1.x = acc[nt][2]*inv1; o1.y = acc[nt][3]*inv1;
        *(float2*)&out[((size_t)b*SS + srow    )*HH + h*DHH + d] = o0;
        *(float2*)&out[((size_t)b*SS + srow + 8)*HH + h*DHH + d] = o1;
    }
}

extern "C" void kernel_launch(void* const* d_in, const int* in_sizes, int n_in,
                              void* d_out, int out_size)
{
    const float* hid  = (const float*)d_in[0];
    const float* bias = (const float*)d_in[1];
    const float* Wq   = (const float*)d_in[2];
    const float* bq   = (const float*)d_in[3];
    const float* Wk   = (const float*)d_in[4];
    const float* bk   = (const float*)d_in[5];
    const float* Wv   = (const float*)d_in[6];
    const float* bv   = (const float*)d_in[7];
    float* out = (float*)d_out;
    (void)in_sizes; (void)n_in; (void)out_size;

    cudaFuncSetAttribute(qkv_kernel, cudaFuncAttributeMaxDynamicSharedMemorySize,
                         QKV_SMEM_U32 * (int)sizeof(unsigned));
    cudaFuncSetAttribute(attn_kernel, cudaFuncAttributeMaxDynamicSharedMemorySize,
                         ATTN_SMEM_U32 * (int)sizeof(unsigned));

    dim3 gc(2048, 4);
    cvt_kernel<<<gc, 256>>>(hid, Wq, Wk, Wv);

    dim3 g1(HH/128, (BB*SS)/128, 3);
    qkv_kernel<<<g1, 256, QKV_SMEM_U32 * (int)sizeof(unsigned)>>>(bq, bk, bv);

    dim3 g2((SS/128)*BB, NHH);
    attn_kernel<<<g2, 256, ATTN_SMEM_U32 * (int)sizeof(unsigned)>>>(bias, out);
}

// round 14
// speedup vs baseline: 1.1394x; 1.1394x over previous
#include <cuda_runtime.h>
#include <cuda_fp16.h>
#include <cstdint>

#define BB   2
#define SS   2048
#define HH   1024
#define NHH  16
#define DHH  64
#define NT   (SS/64)

// fp16 scratch. Q pre-scaled by log2(e)/8 (log2-domain scores).
__device__ __half g_q[BB*NHH*SS*DHH];
__device__ __half g_k[BB*NHH*SS*DHH];
__device__ __half g_v[BB*NHH*SS*DHH];     // V transposed [B,NH,DH,S]
__device__ __half g_hid[BB*SS*HH];
__device__ __half g_wq[HH*HH];
__device__ __half g_wk[HH*HH];
__device__ __half g_wv[HH*HH];

#define L2E 1.4426950408889634f

__device__ __forceinline__ void mma_f16(float* c,
    unsigned a0, unsigned a1, unsigned a2, unsigned a3,
    unsigned b0, unsigned b1)
{
    asm volatile(
        "mma.sync.aligned.m16n8k16.row.col.f32.f16.f16.f32 "
        "{%0,%1,%2,%3}, {%4,%5,%6,%7}, {%8,%9}, {%0,%1,%2,%3};"
        : "+f"(c[0]), "+f"(c[1]), "+f"(c[2]), "+f"(c[3])
        : "r"(a0), "r"(a1), "r"(a2), "r"(a3), "r"(b0), "r"(b1));
}

__device__ __forceinline__ void ldsm_x4(unsigned& r0, unsigned& r1,
                                        unsigned& r2, unsigned& r3, uint32_t a)
{
    asm volatile("ldmatrix.sync.aligned.m8n8.x4.shared.b16 {%0,%1,%2,%3}, [%4];"
        : "=r"(r0), "=r"(r1), "=r"(r2), "=r"(r3) : "r"(a));
}

__device__ __forceinline__ uint32_t smem_u32(const void* p) {
    return (uint32_t)__cvta_generic_to_shared(p);
}
__device__ __forceinline__ void cpa16(uint32_t s, const void* g) {
    asm volatile("cp.async.ca.shared.global [%0], [%1], 16;" :: "r"(s), "l"(g));
}
// streaming variant: bypass L1 allocation (K/V/bias are read-once streams)
__device__ __forceinline__ void cpa16cg(uint32_t s, const void* g) {
    asm volatile("cp.async.cg.shared.global [%0], [%1], 16;" :: "r"(s), "l"(g));
}
#define CP_COMMIT() asm volatile("cp.async.commit_group;")
#define CP_WAIT0()  asm volatile("cp.async.wait_group 0;")
#define CP_WAIT1()  asm volatile("cp.async.wait_group 1;")

__device__ __forceinline__ unsigned packh2(float lo, float hi) {
    __half2 h = __floats2half2_rn(lo, hi);
    return *(unsigned*)&h;
}

__device__ __forceinline__ float fexp2(float y) {
    float r;
    asm("ex2.approx.f32 %0, %1;" : "=f"(r) : "f"(y));
    return r;
}

// ---------------------------------------------------------------------------
// One-time fp32 -> fp16 conversion of hid and the three weight matrices.
// ---------------------------------------------------------------------------
__global__ __launch_bounds__(256) void cvt_kernel(
    const float* __restrict__ hid, const float* __restrict__ wq,
    const float* __restrict__ wk, const float* __restrict__ wv)
{
    const float* src; __half* dst; int n;
    switch (blockIdx.y) {
        case 0:  src = hid; dst = g_hid; n = BB*SS*HH; break;
        case 1:  src = wq;  dst = g_wq;  n = HH*HH;    break;
        case 2:  src = wk;  dst = g_wk;  n = HH*HH;    break;
        default: src = wv;  dst = g_wv;  n = HH*HH;    break;
    }
    int i = (blockIdx.x*256 + threadIdx.x)*8;
    if (i >= n) return;
    float4 v0 = *(const float4*)(src + i);
    float4 v1 = *(const float4*)(src + i + 4);
    uint4 u;
    u.x = packh2(v0.x, v0.y); u.y = packh2(v0.z, v0.w);
    u.z = packh2(v1.x, v1.y); u.w = packh2(v1.z, v1.w);
    *(uint4*)(dst + i) = u;
}

// ---------------------------------------------------------------------------
// QKV projection (unchanged): fp16 GEMM, CTA 128x128, ktile 64, 8 warps 2x4.
// ---------------------------------------------------------------------------
#define KT    64
#define QSTR  36
#define QSTG  (128*QSTR)
#define QKV_SMEM_U32 (4*QSTG)

__global__ __launch_bounds__(256, 2) void qkv_kernel(
    const float* __restrict__ bq, const float* __restrict__ bk,
    const float* __restrict__ bv)
{
    const __half* Wsrc; const float* bsrc;
    if (blockIdx.z == 0)      { Wsrc = g_wq; bsrc = bq; }
    else if (blockIdx.z == 1) { Wsrc = g_wk; bsrc = bk; }
    else                      { Wsrc = g_wv; bsrc = bv; }

    extern __shared__ unsigned smq[];
    unsigned* As  = smq;
    unsigned* Bsm = smq + 2*QSTG;

    const int tid  = threadIdx.x;
    const int warp = tid >> 5;
    const int lane = tid & 31;
    const int gid  = lane >> 2;
    const int tg   = lane & 3;
    const int m0   = blockIdx.y * 128;
    const int n0   = blockIdx.x * 128;
    const int m0w  = (warp >> 2) * 64;
    const int n0w  = (warp & 3) * 32;

    const __half* Ah = g_hid + (size_t)m0 * HH;
    const __half* Bh = Wsrc  + (size_t)n0 * HH;

    const uint32_t as_b = smem_u32(As);
    const uint32_t bs_b = smem_u32(Bsm);

    const int crow = tid >> 3;
    const int cc   = tid & 7;

    #pragma unroll
    for (int it = 0; it < 4; it++) {
        int row = crow + it*32;
        cpa16(as_b + (uint32_t)(row*QSTR + cc*4)*4, Ah + (size_t)row*HH + cc*8);
        cpa16(bs_b + (uint32_t)(row*QSTR + cc*4)*4, Bh + (size_t)row*HH + cc*8);
    }
    CP_COMMIT();

    float acc[4][4][4];
    #pragma unroll
    for (int i = 0; i < 4; i++)
        #pragma unroll
        for (int j = 0; j < 4; j++)
            #pragma unroll
            for (int e = 0; e < 4; e++) acc[i][j][e] = 0.0f;

    const int row16 = lane & 15, c16 = lane >> 4;
    const int lrow8 = lane & 7,  lgrp8 = lane >> 3;
    const uint32_t a_ld = (uint32_t)((m0w + row16)*QSTR)*4 + c16*16;
    const uint32_t b_ld = (uint32_t)((n0w + lrow8)*QSTR)*4 + lgrp8*16;

    for (int kt = 0; kt < HH/KT; kt++) {
        const int cur = kt & 1;

        __syncthreads();
        if (kt + 1 < HH/KT) {
            const int nxt = cur ^ 1;
            const int kof = (kt + 1) * KT;
            #pragma unroll
            for (int it = 0; it < 4; it++) {
                int row = crow + it*32;
                cpa16(as_b + (uint32_t)(nxt*QSTG + row*QSTR + cc*4)*4,
                      Ah + (size_t)row*HH + kof + cc*8);
                cpa16(bs_b + (uint32_t)(nxt*QSTG + row*QSTR + cc*4)*4,
                      Bh + (size_t)row*HH + kof + cc*8);
            }
            CP_COMMIT();
            CP_WAIT1();
        } else {
            CP_WAIT0();
        }
        __syncthreads();

        const uint32_t ab = as_b + (uint32_t)(cur*QSTG)*4;
        const uint32_t bb = bs_b + (uint32_t)(cur*QSTG)*4;

        #pragma unroll
        for (int kp = 0; kp < 2; kp++) {
            unsigned bf[4][4];
            #pragma unroll
            for (int nt = 0; nt < 4; nt++)
                ldsm_x4(bf[nt][0], bf[nt][1], bf[nt][2], bf[nt][3],
                        bb + b_ld + (uint32_t)(nt*8*QSTR)*4 + kp*64);
            #pragma unroll
            for (int kh = 0; kh < 2; kh++) {
                unsigned af[4][4];
                #pragma unroll
                for (int mf = 0; mf < 4; mf++)
                    ldsm_x4(af[mf][0], af[mf][1], af[mf][2], af[mf][3],
                            ab + a_ld + (uint32_t)(mf*16*QSTR)*4 + (kp*2+kh)*32);
                #pragma unroll
                for (int mf = 0; mf < 4; mf++)
                    #pragma unroll
                    for (int nt = 0; nt < 4; nt++)
                        mma_f16(acc[mf][nt], af[mf][0], af[mf][1], af[mf][2],
                                af[mf][3], bf[nt][kh*2], bf[nt][kh*2+1]);
            }
        }
    }

    const int head  = blockIdx.x*2 + (n0w >> 6);
    const int dbase = n0w & 63;

    #pragma unroll
    for (int mf = 0; mf < 4; mf++) {
        int m    = m0 + m0w + mf*16 + gid;
        int bat0 = m >> 11,     srow0 = m & (SS-1);
        int bat1 = (m+8) >> 11, srow1 = (m+8) & (SS-1);

        if (blockIdx.z == 2) {
            size_t base0 = ((size_t)bat0*NHH + head)*DHH;
            size_t base1 = ((size_t)bat1*NHH + head)*DHH;
            #pragma unroll
            for (int nt = 0; nt < 4; nt++) {
                int d = dbase + nt*8 + tg*2;
                int ng = n0 + n0w + nt*8 + tg*2;
                float b0 = bsrc[ng], b1 = bsrc[ng+1];
                g_v[(base0 + d    )*SS + srow0] = __float2half_rn(acc[mf][nt][0]+b0);
                g_v[(base0 + d + 1)*SS + srow0] = __float2half_rn(acc[mf][nt][1]+b1);
                g_v[(base1 + d    )*SS + srow1] = __float2half_rn(acc[mf][nt][2]+b0);
                g_v[(base1 + d + 1)*SS + srow1] = __float2half_rn(acc[mf][nt][3]+b1);
            }
        } else {
            __half* outp = (blockIdx.z == 0) ? g_q : g_k;
            const float qscale = (blockIdx.z == 0) ? (0.125f * L2E) : 1.0f;
            size_t rb0 = (((size_t)bat0*NHH+head)*SS+srow0)*DHH;
            size_t rb1 = (((size_t)bat1*NHH+head)*SS+srow1)*DHH;
            #pragma unroll
            for (int nt = 0; nt < 4; nt++) {
                int d = dbase + nt*8 + tg*2;
                int ng = n0 + n0w + nt*8 + tg*2;
                float b0 = bsrc[ng], b1 = bsrc[ng+1];
                *(unsigned*)&outp[rb0 + d] =
                    packh2((acc[mf][nt][0]+b0)*qscale, (acc[mf][nt][1]+b1)*qscale);
                *(unsigned*)&outp[rb1 + d] =
                    packh2((acc[mf][nt][2]+b0)*qscale, (acc[mf][nt][3]+b1)*qscale);
            }
        }
    }
}

// ---------------------------------------------------------------------------
// Attention (round-12 winner, scalar lsum restored). Two changes:
//  * ONE barrier per iter: wait_group 0 -> barrier -> issue prefetch -> compute.
//    (barrier after the wait gives CTA-wide visibility AND write-after-read
//    safety for the stage being refilled.)
//  * cp.async .cg (no L1 allocation) for the K/V/bias streams.
// ---------------------------------------------------------------------------
#define STR  36
#define BSTR 68
#define SM_K (64*STR)
#define SM_V (64*STR)
#define SM_B (128*BSTR)
#define OFF_K 0
#define OFF_V (2*SM_K)
#define OFF_B (OFF_V + 2*SM_V)
#define ATTN_SMEM_U32 (OFF_B + 2*SM_B)

__global__ __launch_bounds__(256, 2) void attn_kernel(
    const float* __restrict__ bias, float* __restrict__ out)
{
    extern __shared__ unsigned sm[];
    unsigned* Ks = sm + OFF_K;
    unsigned* Vs = sm + OFF_V;
    float*    Bs = (float*)(sm + OFF_B);

    const int tid  = threadIdx.x;
    const int warp = tid >> 5;
    const int lane = tid & 31;
    const int gid  = lane >> 2;
    const int tg   = lane & 3;
    // batch = fastest grid bit: the two CTAs sharing a bias slice are
    // adjacent bids -> same wave, nearby SMs, lockstep bias stream (L2 dedup).
    const int b    = blockIdx.x & 1;
    const int q0   = (blockIdx.x >> 1) * 128;
    const int h    = blockIdx.y;
    const int mw   = warp * 16;
    const int r0   = mw + gid, r1 = r0 + 8;

    const __half* Qg  = g_q + (((size_t)b*NHH + h)*SS + q0)*DHH;
    const __half* Kg  = g_k + (((size_t)b*NHH + h)*SS)*DHH;
    const __half* Vtg = g_v + (((size_t)b*NHH + h)*DHH)*SS;
    const float*  Bg  = bias + ((size_t)h*SS + q0)*SS;

    const uint32_t k_b = smem_u32(Ks);
    const uint32_t v_b = smem_u32(Vs);
    const uint32_t b_b = smem_u32(Bs);

    const int crow = tid >> 3;
    const int ccol = tid & 7;

    // prologue: stage 0 (K/V/bias for kt=0), one group
    #pragma unroll
    for (int it = 0; it < 2; it++) {
        int row = crow + it*32;
        cpa16cg(k_b + (uint32_t)(row*STR + ccol*4)*4, Kg  + (size_t)row*DHH + ccol*8);
        cpa16cg(v_b + (uint32_t)(row*STR + ccol*4)*4, Vtg + (size_t)row*SS  + ccol*8);
    }
    #pragma unroll
    for (int i = 0; i < 8; i++) {
        int idx = tid + i*256;
        int row = idx >> 4, c = idx & 15;
        cpa16cg(b_b + (uint32_t)(row*BSTR + c*4)*4, Bg + (size_t)row*SS + c*4);
    }
    CP_COMMIT();

    unsigned qa[4][4];
    #pragma unroll
    for (int ks = 0; ks < 4; ks++) {
        qa[ks][0] = *(const unsigned*)(Qg + (size_t)r0*DHH + ks*16 + tg*2);
        qa[ks][1] = *(const unsigned*)(Qg + (size_t)r1*DHH + ks*16 + tg*2);
        qa[ks][2] = *(const unsigned*)(Qg + (size_t)r0*DHH + ks*16 + 8 + tg*2);
        qa[ks][3] = *(const unsigned*)(Qg + (size_t)r1*DHH + ks*16 + 8 + tg*2);
    }

    float acc[8][4];
    #pragma unroll
    for (int i = 0; i < 8; i++)
        #pragma unroll
        for (int j = 0; j < 4; j++) acc[i][j] = 0.0f;
    float lsum0 = 0.0f, lsum1 = 0.0f;

    const int lrow8 = lane & 7;
    const int lgrp  = lane >> 3;

    for (int kt = 0; kt < NT; kt++) {
        const int cur = kt & 1;
        const int kv0 = kt * 64;

        CP_WAIT0();          // stage(kt) landed (issued a full iteration ago)
        __syncthreads();     // all warps: wait passed AND done reading stage nxt

        // safe to refill stage nxt now; data flies under this iter's compute
        if (kt + 1 < NT) {
            const int nxt = cur ^ 1;
            #pragma unroll
            for (int it = 0; it < 2; it++) {
                int row = crow + it*32;
                cpa16cg(k_b + (uint32_t)(nxt*SM_K + row*STR + ccol*4)*4,
                        Kg + (size_t)(kv0 + 64 + row)*DHH + ccol*8);
                cpa16cg(v_b + (uint32_t)(nxt*SM_V + row*STR + ccol*4)*4,
                        Vtg + (size_t)row*SS + kv0 + 64 + ccol*8);
            }
            #pragma unroll
            for (int i = 0; i < 8; i++) {
                int idx = tid + i*256;
                int row = idx >> 4, c = idx & 15;
                cpa16cg(b_b + (uint32_t)(nxt*SM_B + row*BSTR + c*4)*4,
                        Bg + (size_t)row*SS + kv0 + 64 + c*4);
            }
            CP_COMMIT();
        }

        const uint32_t kc = k_b + (uint32_t)(cur*SM_K)*4;
        const uint32_t vc = v_b + (uint32_t)(cur*SM_V)*4;
        const float*   Bc = Bs + (size_t)cur*SM_B;

        float s[8][4];
        #pragma unroll
        for (int nt = 0; nt < 8; nt++) {
            s[nt][0] = 0.0f; s[nt][1] = 0.0f; s[nt][2] = 0.0f; s[nt][3] = 0.0f;
            unsigned b0, b1, b2, b3, b4, b5, b6, b7;
            uint32_t base = kc + (uint32_t)((nt*8 + lrow8)*STR)*4 + lgrp*16;
            ldsm_x4(b0, b1, b2, b3, base);
            ldsm_x4(b4, b5, b6, b7, base + 64);
            mma_f16(s[nt], qa[0][0], qa[0][1], qa[0][2], qa[0][3], b0, b1);
            mma_f16(s[nt], qa[1][0], qa[1][1], qa[1][2], qa[1][3], b2, b3);
            mma_f16(s[nt], qa[2][0], qa[2][1], qa[2][2], qa[2][3], b4, b5);
            mma_f16(s[nt], qa[3][0], qa[3][1], qa[3][2], qa[3][3], b6, b7);
        }

        unsigned pa[4][4];
        #pragma unroll
        for (int nt = 0; nt < 8; nt++) {
            int c = nt*8 + tg*2;
            float2 bv0 = *(const float2*)(Bc + (size_t)r0*BSTR + c);
            float2 bv1 = *(const float2*)(Bc + (size_t)r1*BSTR + c);
            float p0 = fexp2(fmaf(bv0.x, L2E, s[nt][0]));
            float p1 = fexp2(fmaf(bv0.y, L2E, s[nt][1]));
            float p2 = fexp2(fmaf(bv1.x, L2E, s[nt][2]));
            float p3 = fexp2(fmaf(bv1.y, L2E, s[nt][3]));
            lsum0 += p0 + p1;
            lsum1 += p2 + p3;
            pa[nt >> 1][(nt & 1)*2 + 0] = packh2(p0, p1);
            pa[nt >> 1][(nt & 1)*2 + 1] = packh2(p2, p3);
        }

        #pragma unroll
        for (int nt = 0; nt < 8; nt++) {
            unsigned b0, b1, b2, b3, b4, b5, b6, b7;
            uint32_t base = vc + (uint32_t)((nt*8 + lrow8)*STR)*4 + lgrp*16;
            ldsm_x4(b0, b1, b2, b3, base);
            ldsm_x4(b4, b5, b6, b7, base + 64);
            mma_f16(acc[nt], pa[0][0], pa[0][1], pa[0][2], pa[0][3], b0, b1);
            mma_f16(acc[nt], pa[1][0], pa[1][1], pa[1][2], pa[1][3], b2, b3);
            mma_f16(acc[nt], pa[2][0], pa[2][1], pa[2][2], pa[2][3], b4, b5);
            mma_f16(acc[nt], pa[3][0], pa[3][1], pa[3][2], pa[3][3], b6, b7);
        }
    }

    lsum0 += __shfl_xor_sync(0xFFFFFFFFu, lsum0, 1);
    lsum0 += __shfl_xor_sync(0xFFFFFFFFu, lsum0, 2);
    lsum1 += __shfl_xor_sync(0xFFFFFFFFu, lsum1, 1);
    lsum1 += __shfl_xor_sync(0xFFFFFFFFu, lsum1, 2);
    float inv0 = 1.0f / lsum0;
    float inv1 = 1.0f / lsum1;

    int srow = q0 + r0;
    #pragma unroll
    for (int nt = 0; nt < 8; nt++) {
        int d = nt*8 + tg*2;
        float2 o0, o1;
        o0.x = acc[nt][0]*inv0; o0.y = acc[nt][1]*inv0;
        o1.x = acc[nt][2]*inv1; o1.y = acc[nt][3]*inv1;
        *(float2*)&out[((size_t)b*SS + srow    )*HH + h*DHH + d] = o0;
        *(float2*)&out[((size_t)b*SS + srow + 8)*HH + h*DHH + d] = o1;
    }
}

extern "C" void kernel_launch(void* const* d_in, const int* in_sizes, int n_in,
                              void* d_out, int out_size)
{
    const float* hid  = (const float*)d_in[0];
    const float* bias = (const float*)d_in[1];
    const float* Wq   = (const float*)d_in[2];
    const float* bq   = (const float*)d_in[3];
    const float* Wk   = (const float*)d_in[4];
    const float* bk   = (const float*)d_in[5];
    const float* Wv   = (const float*)d_in[6];
    const float* bv   = (const float*)d_in[7];
    float* out = (float*)d_out;
    (void)in_sizes; (void)n_in; (void)out_size;

    cudaFuncSetAttribute(qkv_kernel, cudaFuncAttributeMaxDynamicSharedMemorySize,
                         QKV_SMEM_U32 * (int)sizeof(unsigned));
    cudaFuncSetAttribute(attn_kernel, cudaFuncAttributeMaxDynamicSharedMemorySize,
                         ATTN_SMEM_U32 * (int)sizeof(unsigned));

    dim3 gc(2048, 4);
    cvt_kernel<<<gc, 256>>>(hid, Wq, Wk, Wv);

    dim3 g1(HH/128, (BB*SS)/128, 3);
    qkv_kernel<<<g1, 256, QKV_SMEM_U32 * (int)sizeof(unsigned)>>>(bq, bk, bv);

    dim3 g2((SS/128)*BB, NHH);
    attn_kernel<<<g2, 256, ATTN_SMEM_U32 * (int)sizeof(unsigned)>>>(bias, out);
}